// round 6
// baseline (speedup 1.0000x reference)
#include <cuda_runtime.h>
#include <cstddef>

typedef unsigned long long u64;

// ---------------- scratch (device globals; no allocations allowed) ----------
__device__ float g_a1[4096 * 5280];   // post-relu conv1: [b][32][11*15]
__device__ float g_a2[4096 * 2240];   // post-relu conv2: [b][64][5*7]
__device__ float g_a3[4096 * 960];    // post-relu conv3 (flatten CHW): [b][960]
__device__ float g_h [4096 * 512];    // post-relu fc1
__device__ float g_w1t[192 * 32];     // w transposed [k][oc]
__device__ float g_w2t[288 * 64];
__device__ float g_w3t[576 * 64];
__device__ float g_w4t[960 * 512];
__device__ int   g_off1[192];
__device__ int   g_off2[288];
__device__ int   g_off3[576];
__device__ int   g_off4[960];

// ---------------- f32x2 helpers ---------------------------------------------
__device__ __forceinline__ void fma2(u64& d, u64 a, u64 b) {
    asm("fma.rn.f32x2 %0, %1, %2, %3;" : "=l"(d) : "l"(a), "l"(b), "l"(d));
}
__device__ __forceinline__ void add2(u64& d, u64 a) {
    asm("add.rn.f32x2 %0, %1, %2;" : "=l"(d) : "l"(d), "l"(a));
}
__device__ __forceinline__ u64 dup2(float v) {
    u64 r; asm("mov.b64 %0, {%1, %1};" : "=l"(r) : "f"(v)); return r;
}
__device__ __forceinline__ void unpack2(u64 v, float& lo, float& hi) {
    asm("mov.b64 {%0, %1}, %2;" : "=f"(lo), "=f"(hi) : "l"(v));
}

// ---------------- prep: transpose weights + offset tables -------------------
__global__ void prep_kernel(const float* __restrict__ w1,
                            const float* __restrict__ w2,
                            const float* __restrict__ w3,
                            const float* __restrict__ w4) {
    int i = blockIdx.x * blockDim.x + threadIdx.x;
    if (i < 6144)   { int oc = i / 192, k = i % 192; g_w1t[k * 32 + oc] = w1[i]; }
    if (i < 18432)  { int oc = i / 288, k = i % 288; g_w2t[k * 64 + oc] = w2[i]; }
    if (i < 36864)  { int oc = i / 576, k = i % 576; g_w3t[k * 64 + oc] = w3[i]; }
    if (i < 491520) { int oc = i / 960, k = i % 960; g_w4t[k * 512 + oc] = w4[i]; }
    if (i < 192) { int ci = i >> 6, r = i & 63; g_off1[i] = ci * 3072 + (r >> 3) * 64 + (r & 7); }
    if (i < 288) { int ci = i / 9, r = i % 9;  g_off2[i] = ci * 165 + (r / 3) * 15 + r % 3; }
    if (i < 576) { int ci = i / 9, r = i % 9;  g_off3[i] = ci * 35  + (r / 3) * 7  + r % 3; }
    if (i < 960) g_off4[i] = i;
}

// init ave outputs to B*sum(bias)/C (the bias part of the pre-ReLU sums)
__global__ void aveinit_kernel(const float* __restrict__ b1,
                               const float* __restrict__ b2,
                               const float* __restrict__ b3,
                               float* __restrict__ out) {
    int t = threadIdx.x;
    if (t < 165) {
        float s = 0.f; for (int c = 0; c < 32; c++) s += b1[c];
        out[8192 + t] = 4096.f * s / 32.f;
    } else if (t < 200) {
        float s = 0.f; for (int c = 0; c < 64; c++) s += b2[c];
        out[8192 + 165 + (t - 165)] = 4096.f * s / 64.f;
    } else if (t < 215) {
        float s = 0.f; for (int c = 0; c < 64; c++) s += b3[c];
        out[8192 + 200 + (t - 200)] = 4096.f * s / 64.f;
    }
}

// ---------------- unified gather-GEMM (im2col conv / fc) --------------------
// TM=128 fixed: each thread owns 2 f32x2 m-pairs at tx*4 (one LDS.128 per
// k-step, conflict-free 512B warp loads). B duplicated pairs in smem, warp-
// broadcast reads. Double-buffered smem, KC=16, one __syncthreads per chunk.
// Small accumulator footprint (P*TYN <= 8 u64) => high occupancy.
template<int TN, int TY, int KC, int LAYER, bool AVE, int MINB>
__global__ __launch_bounds__(32 * TY, MINB) void net_gemm(
    const float* __restrict__ src_ext,  // only used for LAYER==1 (input x)
    const float* __restrict__ bias,
    float* __restrict__ ave) {

    constexpr int TM  = 128;
    constexpr int NT  = 32 * TY;
    constexpr int TYN = TN / TY;            // n per thread
    constexpr int P   = 2;                  // f32x2 m-pairs per thread
    constexpr int KPT = KC * TM / NT;       // A elems per thread per chunk
    constexpr int NB  = KC * TN / NT;       // B elems per thread per chunk

    constexpr int K        = LAYER == 1 ? 192  : LAYER == 2 ? 288 : LAYER == 3 ? 576 : 960;
    constexpr int NC       = K / KC;
    constexpr int Ntot     = LAYER == 1 ? 32   : LAYER == 4 ? 512 : 64;
    constexpr int npos     = LAYER == 1 ? 165  : LAYER == 2 ? 35  : LAYER == 3 ? 15  : 1;
    constexpr int imgstr   = LAYER == 1 ? 9216 : LAYER == 2 ? 5280: LAYER == 3 ? 2240: 960;
    constexpr int PW       = LAYER == 1 ? 15   : LAYER == 2 ? 7   : LAYER == 3 ? 5   : 1;
    constexpr int rowstep  = LAYER == 1 ? 256  : LAYER == 2 ? 30  : LAYER == 3 ? 7   : 0;
    constexpr int colstep  = LAYER == 1 ? 4    : LAYER == 2 ? 2   : LAYER == 3 ? 1   : 0;
    constexpr int ocs      = LAYER == 1 ? 165  : LAYER == 2 ? 35  : LAYER == 3 ? 15  : 1;
    constexpr int cstride  = LAYER == 1 ? 5280 : LAYER == 2 ? 2240: LAYER == 3 ? 960 : 512;
    constexpr float invC   = LAYER == 1 ? (1.f / 32.f) : (1.f / 64.f);

    const float* wt;
    const int*   offtab;
    const float* src;
    float*       dst;
    if constexpr (LAYER == 1) { wt = g_w1t; offtab = g_off1; src = src_ext; dst = g_a1; }
    if constexpr (LAYER == 2) { wt = g_w2t; offtab = g_off2; src = g_a1;    dst = g_a2; }
    if constexpr (LAYER == 3) { wt = g_w3t; offtab = g_off3; src = g_a2;    dst = g_a3; }
    if constexpr (LAYER == 4) { wt = g_w4t; offtab = g_off4; src = g_a3;    dst = g_h;  }

    extern __shared__ float smem_[];
    float* sa    = smem_;                          // [2][KC][TM]
    u64*   sbd   = (u64*)(sa + 2 * KC * TM);       // [2][KC][TN] dup pairs
    int*   soff  = (int*)(sbd + 2 * KC * TN);      // [K]
    int*   sbase = soff + K;                       // [TM]
    int*   sdst  = sbase + TM;                     // [TM]
    int*   spos  = sdst + TM;                      // [TM] (AVE)
    float* sred  = (float*)(spos + TM);            // [TM] (AVE)

    const int tid = threadIdx.x;
    const int m0 = blockIdx.x * TM;
    const int n0 = blockIdx.y * TN;

    for (int i = tid; i < K; i += NT) soff[i] = offtab[i];
    for (int i = tid; i < TM; i += NT) {
        int m = m0 + i;
        int img = m / npos, pos = m - img * npos;
        int py = pos / PW, px = pos - py * PW;
        sbase[i] = img * imgstr + py * rowstep + px * colstep;
        sdst[i]  = img * cstride + pos;
        if (AVE) { spos[i] = pos; sred[i] = 0.f; }
    }
    __syncthreads();

    const int mloc = tid % TM;
    const int k0f  = (tid / TM) * KPT;
    const int mybase = sbase[mloc];
    const int tx = tid & 31, ty = tid >> 5;

    u64 acc[P][TYN];
#pragma unroll
    for (int p = 0; p < P; p++)
#pragma unroll
        for (int j = 0; j < TYN; j++) acc[p][j] = 0ull;

    int bk[NB], bn[NB];
#pragma unroll
    for (int i = 0; i < NB; i++) { int q = tid + i * NT; bk[i] = q / TN; bn[i] = q % TN; }

    float ra[KPT], rbv[NB];
    // prologue: chunk 0 -> regs -> buf0
#pragma unroll
    for (int j = 0; j < KPT; j++) ra[j] = src[mybase + soff[k0f + j]];
#pragma unroll
    for (int i = 0; i < NB; i++) rbv[i] = wt[bk[i] * Ntot + n0 + bn[i]];
#pragma unroll
    for (int j = 0; j < KPT; j++) sa[(k0f + j) * TM + mloc] = ra[j];
#pragma unroll
    for (int i = 0; i < NB; i++) sbd[bk[i] * TN + bn[i]] = dup2(rbv[i]);
    __syncthreads();

    const float* sax = sa + tx * 4;
    const u64*   sbx = sbd + ty * TYN;

    for (int kc = 0; kc < NC; kc++) {
        const int cur = kc & 1;
        if (kc + 1 < NC) {
            const int kg = (kc + 1) * KC;
#pragma unroll
            for (int j = 0; j < KPT; j++) ra[j] = src[mybase + soff[kg + k0f + j]];
#pragma unroll
            for (int i = 0; i < NB; i++) rbv[i] = wt[(kg + bk[i]) * Ntot + n0 + bn[i]];
        }
        const float* sac = sax + cur * KC * TM;
        const u64*   sbc = sbx + cur * KC * TN;
#pragma unroll
        for (int k = 0; k < KC; k++) {
            ulonglong2 a = *(const ulonglong2*)(sac + k * TM);
            u64 ap0 = a.x, ap1 = a.y;
            u64 bd[TYN];
#pragma unroll
            for (int c = 0; c < TYN / 2; c++) {
                ulonglong2 bv = *(const ulonglong2*)(sbc + k * TN + 2 * c);
                bd[2 * c] = bv.x; bd[2 * c + 1] = bv.y;
            }
#pragma unroll
            for (int j = 0; j < TYN; j++) {
                fma2(acc[0][j], ap0, bd[j]);
                fma2(acc[1][j], ap1, bd[j]);
            }
        }
        if (kc + 1 < NC) {
            const int nb = cur ^ 1;
#pragma unroll
            for (int j = 0; j < KPT; j++) sa[nb * KC * TM + (k0f + j) * TM + mloc] = ra[j];
#pragma unroll
            for (int i = 0; i < NB; i++) sbd[nb * KC * TN + bk[i] * TN + bn[i]] = dup2(rbv[i]);
            __syncthreads();
        }
    }

    // epilogue
    float bnv[TYN];
#pragma unroll
    for (int j = 0; j < TYN; j++) bnv[j] = __ldg(&bias[n0 + ty * TYN + j]);

    int ml[P];
    ml[0] = tx * 4;
    ml[1] = tx * 4 + 2;

    if (AVE) {
#pragma unroll
        for (int p = 0; p < P; p++) {
            u64 rs = acc[p][0];
#pragma unroll
            for (int j = 1; j < TYN; j++) add2(rs, acc[p][j]);
            float rl, rh; unpack2(rs, rl, rh);
            atomicAdd(&sred[ml[p]], rl);
            atomicAdd(&sred[ml[p] + 1], rh);
        }
    }
#pragma unroll
    for (int p = 0; p < P; p++) {
        int dl = sdst[ml[p]], dh = sdst[ml[p] + 1];
#pragma unroll
        for (int j = 0; j < TYN; j++) {
            float lo, hi; unpack2(acc[p][j], lo, hi);
            int nn = n0 + ty * TYN + j;
            dst[dl + nn * ocs] = fmaxf(lo + bnv[j], 0.f);
            dst[dh + nn * ocs] = fmaxf(hi + bnv[j], 0.f);
        }
    }
    if (AVE) {
        __syncthreads();
        for (int i = tid; i < TM; i += NT)
            atomicAdd(&ave[spos[i]], sred[i] * invC);
    }
}

// ---------------- fc2: [4096,512] x [2,512]^T + b ---------------------------
__global__ __launch_bounds__(256) void fc2_kernel(
    const float* __restrict__ w5, const float* __restrict__ b5,
    float* __restrict__ out) {
    int b = blockIdx.x * blockDim.x + threadIdx.x;
    if (b >= 4096) return;
    const float4* h4 = (const float4*)(g_h + (size_t)b * 512);
    const float4* wa = (const float4*)w5;
    const float4* wb = (const float4*)(w5 + 512);
    float s0 = 0.0f, s1 = 0.0f;
#pragma unroll 4
    for (int i = 0; i < 128; i++) {
        float4 h = h4[i];
        float4 a = __ldg(&wa[i]);
        float4 c = __ldg(&wb[i]);
        s0 += h.x * a.x + h.y * a.y + h.z * a.z + h.w * a.w;
        s1 += h.x * c.x + h.y * c.y + h.z * c.z + h.w * c.w;
    }
    out[b * 2 + 0] = s0 + __ldg(&b5[0]);
    out[b * 2 + 1] = s1 + __ldg(&b5[1]);
}

// ---------------- launch ----------------------------------------------------
extern "C" void kernel_launch(void* const* d_in, const int* in_sizes, int n_in,
                              void* d_out, int out_size) {
    const float* x  = (const float*)d_in[0];
    const float* w1 = (const float*)d_in[1];
    const float* b1 = (const float*)d_in[2];
    const float* w2 = (const float*)d_in[3];
    const float* b2 = (const float*)d_in[4];
    const float* w3 = (const float*)d_in[5];
    const float* b3 = (const float*)d_in[6];
    const float* w4 = (const float*)d_in[7];
    const float* b4 = (const float*)d_in[8];
    const float* w5 = (const float*)d_in[9];
    const float* b5 = (const float*)d_in[10];

    float* out  = (float*)d_out;
    float* ave1 = out + 8192;        // 165
    float* ave2 = out + 8192 + 165;  // 35
    float* ave3 = out + 8192 + 200;  // 15

    prep_kernel<<<1920, 256>>>(w1, w2, w3, w4);
    aveinit_kernel<<<1, 256>>>(b1, b2, b3, out);

    // smem bytes = 4*2*KC*128 + 8*2*KC*TN + 4*K + 16*128
    // conv1: TN=32 TY=8  KC=16 -> 16384+8192+768+2048  = 27392 ; grid 5280
    net_gemm<32, 8, 16, 1, true, 4><<<5280, 256, 27392>>>(x, b1, ave1);
    // conv2: TN=64 TY=16 KC=16 -> 16384+16384+1152+2048 = 35968 ; grid 1120
    net_gemm<64, 16, 16, 2, true, 2><<<1120, 512, 35968>>>(nullptr, b2, ave2);
    // conv3: TN=64 TY=16 KC=16 -> 16384+16384+2304+2048 = 37120 ; grid 480
    net_gemm<64, 16, 16, 3, true, 2><<<480, 512, 37120>>>(nullptr, b3, ave3);
    // fc1:   TN=64 TY=16 KC=16 -> 16384+16384+3840+2048 = 38656 ; grid (32,8)
    {
        dim3 grid(32, 8);
        net_gemm<64, 16, 16, 4, false, 2><<<grid, 512, 38656>>>(nullptr, b4, nullptr);
    }
    fc2_kernel<<<16, 256>>>(w5, b5, out);
}

// round 9
// speedup vs baseline: 1.4351x; 1.4351x over previous
#include <cuda_runtime.h>
#include <cuda_bf16.h>
#include <cstdint>

typedef unsigned int u32;

// ---------------- scratch (device globals; no allocations allowed) ----------
__device__ u32  g_a1p[4096u*5280u];   // packed (bf16 hi, bf16 lo) post-relu conv1
__device__ u32  g_a2p[4096u*2240u];   // packed post-relu conv2
__device__ u32  g_a3p[4096u*960u];    // packed post-relu conv3 (CHW flatten)
__device__ float g_h [4096u*512u];    // fp32 post-relu fc1
__device__ __nv_bfloat16 g_bh1[32*192],  g_bl1[32*192];   // weights [n][K] hi/lo
__device__ __nv_bfloat16 g_bh2[64*288],  g_bl2[64*288];
__device__ __nv_bfloat16 g_bh3[64*576],  g_bl3[64*576];
__device__ __nv_bfloat16 g_bh4[512*960], g_bl4[512*960];
__device__ int g_off1[192], g_off2[288], g_off3[576], g_off4[960];

// ---------------- helpers ----------------------------------------------------
__device__ __forceinline__ u32 pack_hl(float v) {
    __nv_bfloat16 h = __float2bfloat16_rn(v);
    float r = v - __bfloat162float(h);
    __nv_bfloat16 l = __float2bfloat16_rn(r);
    return ((u32)__bfloat16_as_ushort(h) << 16) | (u32)__bfloat16_as_ushort(l);
}
__device__ __forceinline__ u32 smem_u32(const void* p) {
    u32 a; asm("{ .reg .u64 t; cvta.to.shared.u64 t, %1; cvt.u32.u64 %0, t; }"
               : "=r"(a) : "l"(p));
    return a;
}

#define LDSM4(r0, r1, r2, r3, a)                                              \
    asm volatile("ldmatrix.sync.aligned.m8n8.x4.shared.b16 {%0,%1,%2,%3}, [%4];" \
        : "=r"(r0), "=r"(r1), "=r"(r2), "=r"(r3) : "r"(a))

#define MMA16816(c, a, b0, b1)                                                \
    asm volatile("mma.sync.aligned.m16n8k16.row.col.f32.bf16.bf16.f32 "       \
        "{%0,%1,%2,%3}, {%4,%5,%6,%7}, {%8,%9}, {%0,%1,%2,%3};"               \
        : "+f"((c)[0]), "+f"((c)[1]), "+f"((c)[2]), "+f"((c)[3])              \
        : "r"((a)[0]), "r"((a)[1]), "r"((a)[2]), "r"((a)[3]),                 \
          "r"(b0), "r"(b1))

// ---------------- prep: split weights to bf16 hi/lo + offset tables ---------
__global__ void prep_w_kernel(const float* __restrict__ w1,
                              const float* __restrict__ w2,
                              const float* __restrict__ w3,
                              const float* __restrict__ w4) {
    for (u32 i = blockIdx.x * blockDim.x + threadIdx.x; i < 491520u;
         i += gridDim.x * blockDim.x) {
        if (i < 6144) {
            float v = w1[i]; __nv_bfloat16 h = __float2bfloat16_rn(v);
            g_bh1[i] = h; g_bl1[i] = __float2bfloat16_rn(v - __bfloat162float(h));
        }
        if (i < 18432) {
            float v = w2[i]; __nv_bfloat16 h = __float2bfloat16_rn(v);
            g_bh2[i] = h; g_bl2[i] = __float2bfloat16_rn(v - __bfloat162float(h));
        }
        if (i < 36864) {
            float v = w3[i]; __nv_bfloat16 h = __float2bfloat16_rn(v);
            g_bh3[i] = h; g_bl3[i] = __float2bfloat16_rn(v - __bfloat162float(h));
        }
        {
            float v = w4[i]; __nv_bfloat16 h = __float2bfloat16_rn(v);
            g_bh4[i] = h; g_bl4[i] = __float2bfloat16_rn(v - __bfloat162float(h));
        }
        if (i < 192) { int ci = i >> 6, r = i & 63; g_off1[i] = ci * 3072 + (r >> 3) * 64 + (r & 7); }
        if (i < 288) { int ci = i / 9, r = i % 9; g_off2[i] = ci * 165 + (r / 3) * 15 + r % 3; }
        if (i < 576) { int ci = i / 9, r = i % 9; g_off3[i] = ci * 35 + (r / 3) * 7 + r % 3; }
        if (i < 960) g_off4[i] = i;
    }
}

__global__ void aveinit_kernel(const float* __restrict__ b1,
                               const float* __restrict__ b2,
                               const float* __restrict__ b3,
                               float* __restrict__ out) {
    int t = threadIdx.x;
    if (t < 165) {
        float s = 0.f; for (int c = 0; c < 32; c++) s += b1[c];
        out[8192 + t] = 4096.f * s / 32.f;
    } else if (t < 200) {
        float s = 0.f; for (int c = 0; c < 64; c++) s += b2[c];
        out[8192 + 165 + (t - 165)] = 4096.f * s / 64.f;
    } else if (t < 215) {
        float s = 0.f; for (int c = 0; c < 64; c++) s += b3[c];
        out[8192 + 200 + (t - 200)] = 4096.f * s / 64.f;
    }
}

// ---------------- unified HMMA gather-GEMM (im2col conv / fc) ---------------
// bf16-split: D = AhBh + AhBl + AlBh in fp32 via mma.sync m16n8k16.
// Block: 256 thr / 8 warps, tile M=128 x NT. smem tiles pitch 80B (16B-aligned,
// conflict-free ldmatrix). K chunks of 32, reg-prefetch of next chunk gather.
template<int LAYER, int NT, int WM>
__global__ __launch_bounds__(256, 2) void conv_hmma(
    const float* __restrict__ src_ext,   // LAYER==1: x (f32)
    const float* __restrict__ bias, float* __restrict__ ave) {

    constexpr int K       = LAYER == 1 ? 192  : LAYER == 2 ? 288 : LAYER == 3 ? 576 : 960;
    constexpr int npos    = LAYER == 1 ? 165  : LAYER == 2 ? 35  : LAYER == 3 ? 15  : 1;
    constexpr int imgstr  = LAYER == 1 ? 9216 : LAYER == 2 ? 5280: LAYER == 3 ? 2240: 960;
    constexpr int PW      = LAYER == 1 ? 15   : LAYER == 2 ? 7   : LAYER == 3 ? 5   : 1;
    constexpr int rowstep = LAYER == 1 ? 256  : LAYER == 2 ? 30  : LAYER == 3 ? 7   : 0;
    constexpr int colstep = LAYER == 1 ? 4    : LAYER == 2 ? 2   : LAYER == 3 ? 1   : 0;
    constexpr int ocs     = LAYER == 1 ? 165  : LAYER == 2 ? 35  : LAYER == 3 ? 15  : 1;
    constexpr int cstride = LAYER == 1 ? 5280 : LAYER == 2 ? 2240: LAYER == 3 ? 960 : 512;
    constexpr float invC  = LAYER == 1 ? (1.f / 32.f) : (1.f / 64.f);
    constexpr bool AVE    = LAYER != 4;
    constexpr int NCH = K / 32;          // 32-k chunks
    constexpr int MT  = WM / 16;         // m16 tiles per warp (1 or 2)
    constexpr int NWN = NT / 32;         // n-warps (1 or 2)
    constexpr int BI  = NT / 16;         // B gather iters per thread
    constexpr int PITCH = 80;            // bytes per smem tile row

    constexpr int A_HI = 0, A_LO = 10240, B_HI = 20480, B_LO = B_HI + NT * PITCH;
    constexpr int TBL  = B_HI + 2 * NT * PITCH;

    const u32* srcp; const u32 *bhp, *blp; const int* offtab;
    if constexpr (LAYER == 1) { srcp = nullptr; offtab = g_off1; bhp = (const u32*)g_bh1; blp = (const u32*)g_bl1; }
    if constexpr (LAYER == 2) { srcp = g_a1p;   offtab = g_off2; bhp = (const u32*)g_bh2; blp = (const u32*)g_bl2; }
    if constexpr (LAYER == 3) { srcp = g_a2p;   offtab = g_off3; bhp = (const u32*)g_bh3; blp = (const u32*)g_bl3; }
    if constexpr (LAYER == 4) { srcp = g_a3p;   offtab = g_off4; bhp = (const u32*)g_bh4; blp = (const u32*)g_bl4; }

    extern __shared__ __align__(128) char smem[];
    const u32 sb = smem_u32(smem);
    int* soff  = (int*)(smem + TBL);   // [K]
    int* sbase = soff + K;             // [128]
    int* sdst  = sbase + 128;          // [128]
    int* spos  = sdst + 128;           // [128]
    float* sred = (float*)(spos + 128);// [128]

    const int tid = threadIdx.x;
    const int wid = tid >> 5, l = tid & 31;
    const int wm = wid / NWN, wn = wid % NWN;
    const int m0 = blockIdx.x * 128;
    const int n0g = (LAYER == 4) ? blockIdx.y * 64 : 0;

    for (int i = tid; i < K; i += 256) soff[i] = offtab[i];
    for (int i = tid; i < 128; i += 256) {
        int m = m0 + i;
        int img = m / npos, pos = m - img * npos;
        int py = pos / PW, px = pos - py * PW;
        sbase[i] = img * imgstr + py * rowstep + px * colstep;
        sdst[i]  = img * cstride + pos;
        spos[i]  = pos;
        sred[i]  = 0.f;
    }
    __syncthreads();

    // gather-thread geometry: row = tid/16 + 16*i, kpair = tid%16
    const int grow = tid >> 4, gj = tid & 15;
    int rb[8];
#pragma unroll
    for (int i = 0; i < 8; i++) rb[i] = sbase[grow + i * 16];

    // ldmatrix lane addresses (ks8=0; +32 bytes for ks8=1)
    u32 aAddr[MT], bAddr[2];
#pragma unroll
    for (int t = 0; t < MT; t++)
        aAddr[t] = sb + A_HI + (u32)(wm * WM + t * 16 + (l & 15)) * PITCH
                 + (u32)((l >> 4) & 1) * 16;
#pragma unroll
    for (int g = 0; g < 2; g++)
        bAddr[g] = sb + B_HI + (u32)(wn * 32 + g * 16 + (l & 7) + ((l >> 4) & 1) * 8) * PITCH
                 + (u32)((l >> 3) & 1) * 16;

    float c[MT][4][4];
#pragma unroll
    for (int t = 0; t < MT; t++)
#pragma unroll
        for (int n = 0; n < 4; n++)
#pragma unroll
            for (int e = 0; e < 4; e++) c[t][n][e] = 0.f;

    u32 ha[8], la[8], hb[BI], lb[BI];

    // ---- gather chunk 0 into regs ----
    {
        int o0 = soff[2 * gj], o1 = soff[2 * gj + 1];
#pragma unroll
        for (int i = 0; i < 8; i++) {
            if constexpr (LAYER == 1) {
                float v0 = src_ext[rb[i] + o0], v1 = src_ext[rb[i] + o1];
                u32 p0 = pack_hl(v0), p1 = pack_hl(v1);
                ha[i] = __byte_perm(p0, p1, 0x7632);
                la[i] = __byte_perm(p0, p1, 0x5410);
            } else {
                u32 p0 = srcp[rb[i] + o0], p1 = srcp[rb[i] + o1];
                ha[i] = __byte_perm(p0, p1, 0x7632);
                la[i] = __byte_perm(p0, p1, 0x5410);
            }
        }
#pragma unroll
        for (int i = 0; i < BI; i++) {
            int widx = (n0g + grow + i * 16) * (K / 2) + gj;
            hb[i] = bhp[widx]; lb[i] = blp[widx];
        }
    }

    for (int cc = 0; cc < NCH; cc++) {
        // ---- regs -> smem tiles ----
#pragma unroll
        for (int i = 0; i < 8; i++) {
            u32 off = (u32)(grow + i * 16) * PITCH + (u32)gj * 4;
            *(u32*)(smem + A_HI + off) = ha[i];
            *(u32*)(smem + A_LO + off) = la[i];
        }
#pragma unroll
        for (int i = 0; i < BI; i++) {
            u32 off = (u32)(grow + i * 16) * PITCH + (u32)gj * 4;
            *(u32*)(smem + B_HI + off) = hb[i];
            *(u32*)(smem + B_LO + off) = lb[i];
        }
        __syncthreads();

        // ---- prefetch next chunk (hides LDG under mma) ----
        if (cc + 1 < NCH) {
            int kg = (cc + 1) * 32;
            int o0 = soff[kg + 2 * gj], o1 = soff[kg + 2 * gj + 1];
#pragma unroll
            for (int i = 0; i < 8; i++) {
                if constexpr (LAYER == 1) {
                    float v0 = src_ext[rb[i] + o0], v1 = src_ext[rb[i] + o1];
                    u32 p0 = pack_hl(v0), p1 = pack_hl(v1);
                    ha[i] = __byte_perm(p0, p1, 0x7632);
                    la[i] = __byte_perm(p0, p1, 0x5410);
                } else {
                    u32 p0 = srcp[rb[i] + o0], p1 = srcp[rb[i] + o1];
                    ha[i] = __byte_perm(p0, p1, 0x7632);
                    la[i] = __byte_perm(p0, p1, 0x5410);
                }
            }
#pragma unroll
            for (int i = 0; i < BI; i++) {
                int widx = (n0g + grow + i * 16) * (K / 2) + (cc + 1) * 16 + gj;
                hb[i] = bhp[widx]; lb[i] = blp[widx];
            }
        }

        // ---- mma phase: 2 k16 steps ----
#pragma unroll
        for (int ks8 = 0; ks8 < 2; ks8++) {
            u32 ah[MT][4], al[MT][4], bhf[2][4], blf[2][4];
#pragma unroll
            for (int t = 0; t < MT; t++) {
                LDSM4(ah[t][0], ah[t][1], ah[t][2], ah[t][3], aAddr[t] + ks8 * 32);
                LDSM4(al[t][0], al[t][1], al[t][2], al[t][3], aAddr[t] + ks8 * 32 + (A_LO - A_HI));
            }
#pragma unroll
            for (int g = 0; g < 2; g++) {
                LDSM4(bhf[g][0], bhf[g][1], bhf[g][2], bhf[g][3], bAddr[g] + ks8 * 32);
                LDSM4(blf[g][0], blf[g][1], blf[g][2], blf[g][3], bAddr[g] + ks8 * 32 + (B_LO - B_HI));
            }
#pragma unroll
            for (int t = 0; t < MT; t++)
#pragma unroll
                for (int g = 0; g < 2; g++)
#pragma unroll
                    for (int h = 0; h < 2; h++) {
                        int nt = g * 2 + h;
                        MMA16816(c[t][nt], ah[t], bhf[g][2 * h], bhf[g][2 * h + 1]);
                        MMA16816(c[t][nt], ah[t], blf[g][2 * h], blf[g][2 * h + 1]);
                        MMA16816(c[t][nt], al[t], bhf[g][2 * h], bhf[g][2 * h + 1]);
                    }
        }
        __syncthreads();
    }

    // ---- epilogue: bias + relu (+ pack), ave row sums ----
#pragma unroll
    for (int t = 0; t < MT; t++) {
        int r0 = wm * WM + t * 16 + (l >> 2);
        int r1 = r0 + 8;
        int db0 = sdst[r0], db1 = sdst[r1];
        float s0 = 0.f, s1 = 0.f;
#pragma unroll
        for (int nt = 0; nt < 4; nt++)
#pragma unroll
            for (int e = 0; e < 2; e++) {
                int n = wn * 32 + nt * 8 + ((l & 3) << 1) + e;
                float v0 = c[t][nt][e], v1 = c[t][nt][2 + e];
                s0 += v0; s1 += v1;
                float bb = __ldg(&bias[n0g + n]);
                float o0 = fmaxf(v0 + bb, 0.f), o1 = fmaxf(v1 + bb, 0.f);
                if constexpr (LAYER == 1) { g_a1p[db0 + n * ocs] = pack_hl(o0); g_a1p[db1 + n * ocs] = pack_hl(o1); }
                if constexpr (LAYER == 2) { g_a2p[db0 + n * ocs] = pack_hl(o0); g_a2p[db1 + n * ocs] = pack_hl(o1); }
                if constexpr (LAYER == 3) { g_a3p[db0 + n * ocs] = pack_hl(o0); g_a3p[db1 + n * ocs] = pack_hl(o1); }
                if constexpr (LAYER == 4) { g_h[db0 + n0g + n] = o0; g_h[db1 + n0g + n] = o1; }
            }
        if constexpr (AVE) {
            atomicAdd(&sred[r0], s0);
            atomicAdd(&sred[r1], s1);
        }
    }
    if constexpr (AVE) {
        __syncthreads();
        if (tid < 128) atomicAdd(&ave[spos[tid]], sred[tid] * invC);
    }
}

// ---------------- fc2: [4096,512] x [2,512]^T + b ---------------------------
__global__ __launch_bounds__(256) void fc2_kernel(
    const float* __restrict__ w5, const float* __restrict__ b5,
    float* __restrict__ out) {
    int b = blockIdx.x * blockDim.x + threadIdx.x;
    if (b >= 4096) return;
    const float4* h4 = (const float4*)(g_h + (size_t)b * 512);
    const float4* wa = (const float4*)w5;
    const float4* wb = (const float4*)(w5 + 512);
    float s0 = 0.0f, s1 = 0.0f;
#pragma unroll 4
    for (int i = 0; i < 128; i++) {
        float4 h = h4[i];
        float4 a = __ldg(&wa[i]);
        float4 c = __ldg(&wb[i]);
        s0 += h.x * a.x + h.y * a.y + h.z * a.z + h.w * a.w;
        s1 += h.x * c.x + h.y * c.y + h.z * c.z + h.w * c.w;
    }
    out[b * 2 + 0] = s0 + __ldg(&b5[0]);
    out[b * 2 + 1] = s1 + __ldg(&b5[1]);
}

// ---------------- launch ----------------------------------------------------
extern "C" void kernel_launch(void* const* d_in, const int* in_sizes, int n_in,
                              void* d_out, int out_size) {
    const float* x  = (const float*)d_in[0];
    const float* w1 = (const float*)d_in[1];
    const float* b1 = (const float*)d_in[2];
    const float* w2 = (const float*)d_in[3];
    const float* b2 = (const float*)d_in[4];
    const float* w3 = (const float*)d_in[5];
    const float* b3 = (const float*)d_in[6];
    const float* w4 = (const float*)d_in[7];
    const float* b4 = (const float*)d_in[8];
    const float* w5 = (const float*)d_in[9];
    const float* b5 = (const float*)d_in[10];

    float* out  = (float*)d_out;
    float* ave1 = out + 8192;        // 165
    float* ave2 = out + 8192 + 165;  // 35
    float* ave3 = out + 8192 + 200;  // 15

    prep_w_kernel<<<480, 256>>>(w1, w2, w3, w4);
    aveinit_kernel<<<1, 256>>>(b1, b2, b3, out);

    // dynamic smem: 20480 (A) + 2*NT*80 (B) + 4*K + 2048 (tables)
    const int sm1 = 20480 + 2 * 32 * 80 + 4 * 192 + 2048;   // 28416
    const int sm2 = 20480 + 2 * 64 * 80 + 4 * 288 + 2048;   // 33920
    const int sm3 = 20480 + 2 * 64 * 80 + 4 * 576 + 2048;   // 35072
    const int sm4 = 20480 + 2 * 64 * 80 + 4 * 960 + 2048;   // 36608

    conv_hmma<1, 32, 16><<<5280, 256, sm1>>>(x, b1, ave1);       // M=675840
    conv_hmma<2, 64, 32><<<1120, 256, sm2>>>(nullptr, b2, ave2); // M=143360
    conv_hmma<3, 64, 32><<<480, 256, sm3>>>(nullptr, b3, ave3);  // M=61440
    {
        dim3 grid(32, 8);                                        // M=4096, N=512
        conv_hmma<4, 64, 32><<<grid, 256, sm4>>>(nullptr, b4, nullptr);
    }
    fc2_kernel<<<16, 256>>>(w5, b5, out);
}

// round 10
// speedup vs baseline: 2.3540x; 1.6403x over previous
#include <cuda_runtime.h>
#include <cuda_bf16.h>
#include <cstdint>

typedef unsigned int u32;

// ---------------- scratch (device globals; no allocations allowed) ----------
__device__ u32  g_a1p[4096u*5280u];   // packed (bf16 hi, bf16 lo) post-relu conv1
__device__ u32  g_a2p[4096u*2240u];   // packed post-relu conv2
__device__ u32  g_a3p[4096u*960u];    // packed post-relu conv3 (CHW flatten)
__device__ float g_h [4096u*512u];    // fp32 post-relu fc1
__device__ __nv_bfloat16 g_bh1[32*192],  g_bl1[32*192];   // weights [n][K] hi/lo
__device__ __nv_bfloat16 g_bh2[64*288],  g_bl2[64*288];
__device__ __nv_bfloat16 g_bh3[64*576],  g_bl3[64*576];
__device__ __nv_bfloat16 g_bh4[512*960], g_bl4[512*960];
__device__ int g_off1[192], g_off2[288], g_off3[576], g_off4[960];

// ---------------- helpers ----------------------------------------------------
__device__ __forceinline__ u32 pack_hl(float v) {
    __nv_bfloat16 h = __float2bfloat16_rn(v);
    float r = v - __bfloat162float(h);
    __nv_bfloat16 l = __float2bfloat16_rn(r);
    return ((u32)__bfloat16_as_ushort(h) << 16) | (u32)__bfloat16_as_ushort(l);
}
__device__ __forceinline__ u32 smem_u32(const void* p) {
    u32 a; asm("{ .reg .u64 t; cvta.to.shared.u64 t, %1; cvt.u32.u64 %0, t; }"
               : "=r"(a) : "l"(p));
    return a;
}

#define LDSM4(r0, r1, r2, r3, a)                                              \
    asm volatile("ldmatrix.sync.aligned.m8n8.x4.shared.b16 {%0,%1,%2,%3}, [%4];" \
        : "=r"(r0), "=r"(r1), "=r"(r2), "=r"(r3) : "r"(a))

#define MMA16816(c, a, b0, b1)                                                \
    asm volatile("mma.sync.aligned.m16n8k16.row.col.f32.bf16.bf16.f32 "       \
        "{%0,%1,%2,%3}, {%4,%5,%6,%7}, {%8,%9}, {%0,%1,%2,%3};"               \
        : "+f"((c)[0]), "+f"((c)[1]), "+f"((c)[2]), "+f"((c)[3])              \
        : "r"((a)[0]), "r"((a)[1]), "r"((a)[2]), "r"((a)[3]),                 \
          "r"(b0), "r"(b1))

// ---------------- prep: split weights to bf16 hi/lo + offset tables ---------
__global__ void prep_w_kernel(const float* __restrict__ w1,
                              const float* __restrict__ w2,
                              const float* __restrict__ w3,
                              const float* __restrict__ w4) {
    for (u32 i = blockIdx.x * blockDim.x + threadIdx.x; i < 491520u;
         i += gridDim.x * blockDim.x) {
        if (i < 6144) {
            float v = w1[i]; __nv_bfloat16 h = __float2bfloat16_rn(v);
            g_bh1[i] = h; g_bl1[i] = __float2bfloat16_rn(v - __bfloat162float(h));
        }
        if (i < 18432) {
            float v = w2[i]; __nv_bfloat16 h = __float2bfloat16_rn(v);
            g_bh2[i] = h; g_bl2[i] = __float2bfloat16_rn(v - __bfloat162float(h));
        }
        if (i < 36864) {
            float v = w3[i]; __nv_bfloat16 h = __float2bfloat16_rn(v);
            g_bh3[i] = h; g_bl3[i] = __float2bfloat16_rn(v - __bfloat162float(h));
        }
        {
            float v = w4[i]; __nv_bfloat16 h = __float2bfloat16_rn(v);
            g_bh4[i] = h; g_bl4[i] = __float2bfloat16_rn(v - __bfloat162float(h));
        }
        if (i < 192) { int ci = i >> 6, r = i & 63; g_off1[i] = ci * 3072 + (r >> 3) * 64 + (r & 7); }
        if (i < 288) { int ci = i / 9, r = i % 9; g_off2[i] = ci * 165 + (r / 3) * 15 + r % 3; }
        if (i < 576) { int ci = i / 9, r = i % 9; g_off3[i] = ci * 35 + (r / 3) * 7 + r % 3; }
        if (i < 960) g_off4[i] = i;
    }
}

__global__ void aveinit_kernel(const float* __restrict__ b1,
                               const float* __restrict__ b2,
                               const float* __restrict__ b3,
                               float* __restrict__ out) {
    int t = threadIdx.x;
    if (t < 165) {
        float s = 0.f; for (int c = 0; c < 32; c++) s += b1[c];
        out[8192 + t] = 4096.f * s / 32.f;
    } else if (t < 200) {
        float s = 0.f; for (int c = 0; c < 64; c++) s += b2[c];
        out[8192 + 165 + (t - 165)] = 4096.f * s / 64.f;
    } else if (t < 215) {
        float s = 0.f; for (int c = 0; c < 64; c++) s += b3[c];
        out[8192 + 200 + (t - 200)] = 4096.f * s / 64.f;
    }
}

// ---------------- unified HMMA gather-GEMM (im2col conv / fc) ---------------
// bf16-split: D = AhBh + AhBl + AlBh in fp32 via mma.sync m16n8k16.
// Gather lanes cover 8m x 4kw (coalesced LDG, conflict-free STS). Double-
// buffered smem, one __syncthreads per 32-k chunk. Tiles pitch 80B.
template<int LAYER, int NT, int WM>
__global__ __launch_bounds__(256, 2) void conv_hmma(
    const float* __restrict__ src_ext,   // LAYER==1: x (f32)
    const float* __restrict__ bias, float* __restrict__ ave) {

    constexpr int K       = LAYER == 1 ? 192  : LAYER == 2 ? 288 : LAYER == 3 ? 576 : 960;
    constexpr int npos    = LAYER == 1 ? 165  : LAYER == 2 ? 35  : LAYER == 3 ? 15  : 1;
    constexpr int imgstr  = LAYER == 1 ? 9216 : LAYER == 2 ? 5280: LAYER == 3 ? 2240: 960;
    constexpr int PW      = LAYER == 1 ? 15   : LAYER == 2 ? 7   : LAYER == 3 ? 5   : 1;
    constexpr int rowstep = LAYER == 1 ? 256  : LAYER == 2 ? 30  : LAYER == 3 ? 7   : 0;
    constexpr int colstep = LAYER == 1 ? 4    : LAYER == 2 ? 2   : LAYER == 3 ? 1   : 0;
    constexpr int ocs     = LAYER == 1 ? 165  : LAYER == 2 ? 35  : LAYER == 3 ? 15  : 1;
    constexpr int cstride = LAYER == 1 ? 5280 : LAYER == 2 ? 2240: LAYER == 3 ? 960 : 512;
    constexpr float invC  = LAYER == 1 ? (1.f / 32.f) : (1.f / 64.f);
    constexpr bool AVE    = LAYER != 4;
    constexpr int NCH = K / 32;
    constexpr int MT  = WM / 16;
    constexpr int NWN = NT / 32;
    constexpr int PITCH = 80;
    constexpr int A_HI = 0, A_LO = 10240, B_HI = 20480;
    constexpr int BUF = 20480 + NT * 160;     // per-buffer bytes

    const u32* srcp; const char *bhp, *blp; const int* offtab;
    if constexpr (LAYER == 1) { srcp = nullptr; offtab = g_off1; bhp = (const char*)g_bh1; blp = (const char*)g_bl1; }
    if constexpr (LAYER == 2) { srcp = g_a1p;   offtab = g_off2; bhp = (const char*)g_bh2; blp = (const char*)g_bl2; }
    if constexpr (LAYER == 3) { srcp = g_a2p;   offtab = g_off3; bhp = (const char*)g_bh3; blp = (const char*)g_bl3; }
    if constexpr (LAYER == 4) { srcp = g_a3p;   offtab = g_off4; bhp = (const char*)g_bh4; blp = (const char*)g_bl4; }

    extern __shared__ __align__(128) char smem[];
    const u32 sb = smem_u32(smem);
    int* soff  = (int*)(smem + 2 * BUF);  // [K]
    int* sbase = soff + K;                // [128]
    int* sdst  = sbase + 128;             // [128]
    int* spos  = sdst + 128;              // [128]
    float* sred = (float*)(spos + 128);   // [128]

    const int tid = threadIdx.x;
    const int wid = tid >> 5, l = tid & 31;
    const int wm = wid / NWN, wn = wid % NWN;
    const int m0 = blockIdx.x * 128;
    const int n0g = (LAYER == 4) ? blockIdx.y * 64 : 0;

    for (int i = tid; i < K; i += 256) soff[i] = offtab[i];
    for (int i = tid; i < 128; i += 256) {
        int m = m0 + i;
        int img = m / npos, pos = m - img * npos;
        int py = pos / PW, px = pos - py * PW;
        sbase[i] = img * imgstr + py * rowstep + px * colstep;
        sdst[i]  = img * cstride + pos;
        spos[i]  = pos;
        sred[i]  = 0.f;
    }
    __syncthreads();

    // gather geometry: m = wid*16 + (l>>2) + 8i (i<2), kw = (l&3) + 4j (j<4)
    const int gm = wid * 16 + (l >> 2);
    const int gk = l & 3;
    int rb[2] = { sbase[gm], sbase[gm + 8] };
    // B: thread -> (row n, 16B block)
    const int bn = tid >> 2, bblk = tid & 3;
    const bool bact = tid < NT * 4;

    // ldmatrix lane addresses (buffer 0; add bufoff + ks8*32 at use)
    u32 aAddr[MT], bAddr[2];
#pragma unroll
    for (int t = 0; t < MT; t++)
        aAddr[t] = sb + A_HI + (u32)(wm * WM + t * 16 + (l & 15)) * PITCH
                 + (u32)((l >> 4) & 1) * 16;
#pragma unroll
    for (int g = 0; g < 2; g++)
        bAddr[g] = sb + B_HI + (u32)(wn * 32 + g * 16 + (l & 7) + ((l >> 4) & 1) * 8) * PITCH
                 + (u32)((l >> 3) & 1) * 16;

    float c[MT][4][4];
#pragma unroll
    for (int t = 0; t < MT; t++)
#pragma unroll
        for (int n = 0; n < 4; n++)
#pragma unroll
            for (int e = 0; e < 4; e++) c[t][n][e] = 0.f;

    u32 ha[8], la[8];
    uint4 hb4, lb4;

    // ---- gather of one chunk into regs ----
    auto gather = [&](int cc) {
        const int kc = cc * 32;
#pragma unroll
        for (int i = 0; i < 2; i++)
#pragma unroll
            for (int j = 0; j < 4; j++) {
                int kw = gk + 4 * j;
                int e = i * 4 + j;
                u32 p0, p1;
                if constexpr (LAYER == 1) {
                    int o0 = soff[kc + 2 * kw];
                    float2 v = *(const float2*)(src_ext + rb[i] + o0);
                    p0 = pack_hl(v.x); p1 = pack_hl(v.y);
                } else if constexpr (LAYER == 4) {
                    uint2 w = *(const uint2*)(srcp + rb[i] + kc + 2 * kw);
                    p0 = w.x; p1 = w.y;
                } else {
                    int o0 = soff[kc + 2 * kw], o1 = soff[kc + 2 * kw + 1];
                    p0 = srcp[rb[i] + o0]; p1 = srcp[rb[i] + o1];
                }
                ha[e] = __byte_perm(p0, p1, 0x7632);
                la[e] = __byte_perm(p0, p1, 0x5410);
            }
        if (bact) {
            size_t boff = (size_t)(n0g + bn) * (2 * K) + cc * 64 + bblk * 16;
            hb4 = *(const uint4*)(bhp + boff);
            lb4 = *(const uint4*)(blp + boff);
        }
    };
    // ---- regs -> smem buffer ----
    auto store = [&](int buf) {
        char* base = smem + buf * BUF;
#pragma unroll
        for (int i = 0; i < 2; i++)
#pragma unroll
            for (int j = 0; j < 4; j++) {
                u32 off = (u32)(gm + 8 * i) * PITCH + (u32)(gk + 4 * j) * 4;
                *(u32*)(base + A_HI + off) = ha[i * 4 + j];
                *(u32*)(base + A_LO + off) = la[i * 4 + j];
            }
        if (bact) {
            u32 off = (u32)bn * PITCH + (u32)bblk * 16;
            *(uint4*)(base + B_HI + off) = hb4;
            *(uint4*)(base + B_HI + NT * PITCH + off) = lb4;
        }
    };

    gather(0);
    store(0);
    __syncthreads();

    for (int cc = 0; cc < NCH; cc++) {
        if (cc + 1 < NCH) gather(cc + 1);           // LDG latency hides under mma
        const u32 bufoff = (u32)(cc & 1) * BUF;
#pragma unroll
        for (int ks8 = 0; ks8 < 2; ks8++) {
            u32 ah[MT][4], al[MT][4], bhf[2][4], blf[2][4];
#pragma unroll
            for (int t = 0; t < MT; t++) {
                LDSM4(ah[t][0], ah[t][1], ah[t][2], ah[t][3], aAddr[t] + bufoff + ks8 * 32);
                LDSM4(al[t][0], al[t][1], al[t][2], al[t][3], aAddr[t] + bufoff + ks8 * 32 + (A_LO - A_HI));
            }
#pragma unroll
            for (int g = 0; g < 2; g++) {
                LDSM4(bhf[g][0], bhf[g][1], bhf[g][2], bhf[g][3], bAddr[g] + bufoff + ks8 * 32);
                LDSM4(blf[g][0], blf[g][1], blf[g][2], blf[g][3], bAddr[g] + bufoff + ks8 * 32 + NT * PITCH);
            }
#pragma unroll
            for (int t = 0; t < MT; t++)
#pragma unroll
                for (int g = 0; g < 2; g++)
#pragma unroll
                    for (int h = 0; h < 2; h++) {
                        int nt = g * 2 + h;
                        MMA16816(c[t][nt], ah[t], bhf[g][2 * h], bhf[g][2 * h + 1]);
                        MMA16816(c[t][nt], ah[t], blf[g][2 * h], blf[g][2 * h + 1]);
                        MMA16816(c[t][nt], al[t], bhf[g][2 * h], bhf[g][2 * h + 1]);
                    }
        }
        if (cc + 1 < NCH) store((cc + 1) & 1);
        __syncthreads();
    }

    // ---- epilogue: bias + relu (+ pack), ave row sums ----
#pragma unroll
    for (int t = 0; t < MT; t++) {
        int r0 = wm * WM + t * 16 + (l >> 2);
        int r1 = r0 + 8;
        int db0 = sdst[r0], db1 = sdst[r1];
        float s0 = 0.f, s1 = 0.f;
#pragma unroll
        for (int nt = 0; nt < 4; nt++)
#pragma unroll
            for (int e = 0; e < 2; e++) {
                int n = wn * 32 + nt * 8 + ((l & 3) << 1) + e;
                float v0 = c[t][nt][e], v1 = c[t][nt][2 + e];
                s0 += v0; s1 += v1;
                float bb = __ldg(&bias[n0g + n]);
                float o0 = fmaxf(v0 + bb, 0.f), o1 = fmaxf(v1 + bb, 0.f);
                if constexpr (LAYER == 1) { g_a1p[db0 + n * ocs] = pack_hl(o0); g_a1p[db1 + n * ocs] = pack_hl(o1); }
                if constexpr (LAYER == 2) { g_a2p[db0 + n * ocs] = pack_hl(o0); g_a2p[db1 + n * ocs] = pack_hl(o1); }
                if constexpr (LAYER == 3) { g_a3p[db0 + n * ocs] = pack_hl(o0); g_a3p[db1 + n * ocs] = pack_hl(o1); }
                if constexpr (LAYER == 4) { g_h[db0 + n0g + n] = o0; g_h[db1 + n0g + n] = o1; }
            }
        if constexpr (AVE) {
            atomicAdd(&sred[r0], s0);
            atomicAdd(&sred[r1], s1);
        }
    }
    if constexpr (AVE) {
        __syncthreads();
        if (tid < 128) atomicAdd(&ave[spos[tid]], sred[tid] * invC);
    }
}

// ---------------- fc2: [4096,512] x [2,512]^T + b ---------------------------
__global__ __launch_bounds__(256) void fc2_kernel(
    const float* __restrict__ w5, const float* __restrict__ b5,
    float* __restrict__ out) {
    int b = blockIdx.x * blockDim.x + threadIdx.x;
    if (b >= 4096) return;
    const float4* h4 = (const float4*)(g_h + (size_t)b * 512);
    const float4* wa = (const float4*)w5;
    const float4* wb = (const float4*)(w5 + 512);
    float s0 = 0.0f, s1 = 0.0f;
#pragma unroll 4
    for (int i = 0; i < 128; i++) {
        float4 h = h4[i];
        float4 a = __ldg(&wa[i]);
        float4 c = __ldg(&wb[i]);
        s0 += h.x * a.x + h.y * a.y + h.z * a.z + h.w * a.w;
        s1 += h.x * c.x + h.y * c.y + h.z * c.z + h.w * c.w;
    }
    out[b * 2 + 0] = s0 + __ldg(&b5[0]);
    out[b * 2 + 1] = s1 + __ldg(&b5[1]);
}

// ---------------- launch ----------------------------------------------------
extern "C" void kernel_launch(void* const* d_in, const int* in_sizes, int n_in,
                              void* d_out, int out_size) {
    const float* x  = (const float*)d_in[0];
    const float* w1 = (const float*)d_in[1];
    const float* b1 = (const float*)d_in[2];
    const float* w2 = (const float*)d_in[3];
    const float* b2 = (const float*)d_in[4];
    const float* w3 = (const float*)d_in[5];
    const float* b3 = (const float*)d_in[6];
    const float* w4 = (const float*)d_in[7];
    const float* b4 = (const float*)d_in[8];
    const float* w5 = (const float*)d_in[9];
    const float* b5 = (const float*)d_in[10];

    float* out  = (float*)d_out;
    float* ave1 = out + 8192;        // 165
    float* ave2 = out + 8192 + 165;  // 35
    float* ave3 = out + 8192 + 200;  // 15

    prep_w_kernel<<<480, 256>>>(w1, w2, w3, w4);
    aveinit_kernel<<<1, 256>>>(b1, b2, b3, out);

    // dynamic smem: 2*BUF + 4*K + 2048 ; BUF = 20480 + NT*160
    const int sm1 = 2 * (20480 + 32 * 160) + 4 * 192 + 2048;   // 54016
    const int sm2 = 2 * (20480 + 64 * 160) + 4 * 288 + 2048;   // 64640
    const int sm3 = 2 * (20480 + 64 * 160) + 4 * 576 + 2048;   // 65792
    const int sm4 = 2 * (20480 + 64 * 160) + 4 * 960 + 2048;   // 67328
    cudaFuncSetAttribute(conv_hmma<1, 32, 16>, cudaFuncAttributeMaxDynamicSharedMemorySize, sm1);
    cudaFuncSetAttribute(conv_hmma<2, 64, 32>, cudaFuncAttributeMaxDynamicSharedMemorySize, sm2);
    cudaFuncSetAttribute(conv_hmma<3, 64, 32>, cudaFuncAttributeMaxDynamicSharedMemorySize, sm3);
    cudaFuncSetAttribute(conv_hmma<4, 64, 32>, cudaFuncAttributeMaxDynamicSharedMemorySize, sm4);

    conv_hmma<1, 32, 16><<<5280, 256, sm1>>>(x, b1, ave1);       // M=675840
    conv_hmma<2, 64, 32><<<1120, 256, sm2>>>(nullptr, b2, ave2); // M=143360
    conv_hmma<3, 64, 32><<<480, 256, sm3>>>(nullptr, b3, ave3);  // M=61440
    {
        dim3 grid(32, 8);                                        // M=4096, N=512
        conv_hmma<4, 64, 32><<<grid, 256, sm4>>>(nullptr, b4, nullptr);
    }
    fc2_kernel<<<16, 256>>>(w5, b5, out);
}